// round 2
// baseline (speedup 1.0000x reference)
#include <cuda_runtime.h>

#define NN 10000
#define NE 160000

// constants (hand-derived; see analysis)
#define SILU_C_F   1.6765867f
#define INV_S8     0.35355339059327373f
#define INV_S32    0.17677669529663687f
#define INV_S96    0.10206207261596575f
#define INV_S128   0.08838834764831845f
#define INV_S3     0.57735026918962576f
#define S3_DIV_S5  0.77459666924148338f   // sqrt(3/5)
#define IS2        0.70710678118654752f   // 1/sqrt(2)
#define IS6        0.40824829046386302f   // 1/sqrt(6)
#define C_S        0.38268343236508977f   // sin(pi/8)
#define C_X        0.92387953251128676f   // cos(pi/8)

// scratch (no allocation allowed -> device globals)
__device__ float g_y[NN * 160];     // lin1 output per node: [y0(64) | y1(32x3)]
__device__ float g_s[NN * 160];     // self-connection:      [s0(64) | s1(32x3)]
__device__ float g_agg[NN * 960];   // scattered edge features

__device__ __forceinline__ void red4(float* p, float a, float b, float c, float d) {
    asm volatile("red.global.add.v4.f32 [%0], {%1,%2,%3,%4};"
                 :: "l"(p), "f"(a), "f"(b), "f"(c), "f"(d) : "memory");
}

// ---------------- zero agg ----------------
__global__ void k_zero() {
    int i = blockIdx.x * blockDim.x + threadIdx.x;
    const int n4 = NN * 960 / 4;
    if (i < n4) reinterpret_cast<float4*>(g_agg)[i] = make_float4(0.f, 0.f, 0.f, 0.f);
}

// ---------------- node pre-linear: y (lin1) and s (sc) ----------------
__global__ __launch_bounds__(160) void k_node(
    const float* __restrict__ node_input, const float* __restrict__ node_attr,
    const float* __restrict__ sc_w0, const float* __restrict__ sc_w1,
    const float* __restrict__ lin1_w0, const float* __restrict__ lin1_w1)
{
    __shared__ float xs[160];
    int n = blockIdx.x, t = threadIdx.x;
    xs[t] = node_input[n * 160 + t];
    __syncthreads();
    float a = node_attr[n];
    if (t < 64) {
        float ay = 0.f, as = 0.f;
        #pragma unroll
        for (int u = 0; u < 64; u++) {
            float xv = xs[u];
            ay = fmaf(xv, lin1_w0[u * 64 + t], ay);
            as = fmaf(xv, sc_w0[u * 64 + t], as);
        }
        g_y[n * 160 + t] = ay * a * 0.125f;
        g_s[n * 160 + t] = as * a * 0.125f;
    } else {
        int j = t - 64, v = j / 3, i = j - 3 * v;
        float ay = 0.f, as = 0.f;
        #pragma unroll
        for (int u = 0; u < 32; u++) {
            float xv = xs[64 + u * 3 + i];
            ay = fmaf(xv, lin1_w1[u * 32 + v], ay);
            as = fmaf(xv, sc_w1[u * 32 + v], as);
        }
        g_y[n * 160 + t] = ay * a * INV_S32;
        g_s[n * 160 + t] = as * a * INV_S32;
    }
}

// ---------------- fused edge kernel: weight MLP + TP paths + scatter ----------------
__global__ __launch_bounds__(128) void k_edge(
    const float* __restrict__ edge_attr,
    const float* __restrict__ ele,
    const int*   __restrict__ edge_src,
    const int*   __restrict__ edge_dst,
    const float* __restrict__ fc_w0,
    const float* __restrict__ fc_w1)
{
    extern __shared__ float sw[];
    float* s_w1 = sw;              // 64*320
    float* s_w0 = sw + 64 * 320;   // 8*64
    int tid = threadIdx.x;
    for (int i = tid; i < 64 * 320; i += 128) s_w1[i] = fc_w1[i];
    for (int i = tid; i < 512;      i += 128) s_w0[i] = fc_w0[i];
    __syncthreads();

    int e = blockIdx.x * 128 + tid;
    if (e >= NE) return;

    // edge length embedding
    float el[8];
    {
        const float4* elp = reinterpret_cast<const float4*>(ele + e * 8);
        float4 ea = elp[0], eb = elp[1];
        el[0] = ea.x; el[1] = ea.y; el[2] = ea.z; el[3] = ea.w;
        el[4] = eb.x; el[5] = eb.y; el[6] = eb.z; el[7] = eb.w;
    }

    // h[c] = silu((ele . fc_w0[:,c]) / sqrt(8)) * SILU_C / sqrt(64) / sqrt(AVG_DEGREE)
    float h[64];
    #pragma unroll
    for (int c = 0; c < 64; c++) {
        float z = 0.f;
        #pragma unroll
        for (int k = 0; k < 8; k++) z = fmaf(el[k], s_w0[k * 64 + c], z);
        z *= INV_S8;
        float sg = __fdividef(1.f, 1.f + __expf(-z));
        h[c] = z * sg * (SILU_C_F * 0.03125f);   // * 1/8 * 1/4
    }

    int src = edge_src[e], dst = edge_dst[e];
    const float* ys = g_y + src * 160;
    float* ag = g_agg + dst * 960;

    float e0  = edge_attr[e * 9 + 0];
    float e1a = edge_attr[e * 9 + 1], e1b = edge_attr[e * 9 + 2], e1c = edge_attr[e * 9 + 3];
    float p0  = edge_attr[e * 9 + 4], p1 = edge_attr[e * 9 + 5], p2 = edge_attr[e * 9 + 6];
    float p3  = edge_attr[e * 9 + 7], p4 = edge_attr[e * 9 + 8];

    // ===== scalar-source paths: k0 (cols 0:64), k2 (96:288), k5 (480:800) =====
    for (int u0 = 0; u0 < 64; u0 += 4) {
        float4 yv = *reinterpret_cast<const float4*>(ys + u0);
        float yy[4] = {yv.x, yv.y, yv.z, yv.w};
        float wa[4] = {0,0,0,0}, wb[4] = {0,0,0,0}, wc[4] = {0,0,0,0};
        const float* wrow = s_w1 + u0;
        #pragma unroll
        for (int c = 0; c < 64; c++) {
            float hc = h[c];
            const float* r = wrow + c * 320;
            float4 q0 = *reinterpret_cast<const float4*>(r);        // w[:,0:64]
            float4 q1 = *reinterpret_cast<const float4*>(r + 64);   // w[:,64:128]
            float4 q2 = *reinterpret_cast<const float4*>(r + 128);  // w[:,128:192]
            wa[0] = fmaf(hc, q0.x, wa[0]); wa[1] = fmaf(hc, q0.y, wa[1]);
            wa[2] = fmaf(hc, q0.z, wa[2]); wa[3] = fmaf(hc, q0.w, wa[3]);
            wb[0] = fmaf(hc, q1.x, wb[0]); wb[1] = fmaf(hc, q1.y, wb[1]);
            wb[2] = fmaf(hc, q1.z, wb[2]); wb[3] = fmaf(hc, q1.w, wb[3]);
            wc[0] = fmaf(hc, q2.x, wc[0]); wc[1] = fmaf(hc, q2.y, wc[1]);
            wc[2] = fmaf(hc, q2.z, wc[2]); wc[3] = fmaf(hc, q2.w, wc[3]);
        }
        // k0[u] = y0[u] * e0 * w0[u]
        red4(ag + u0, yy[0]*e0*wa[0], yy[1]*e0*wa[1], yy[2]*e0*wa[2], yy[3]*e0*wa[3]);
        // k2[u][k] = y0[u] * w2[u] * e1[k]   (cols 96 + 3u + k)
        {
            float t2[12];
            #pragma unroll
            for (int d = 0; d < 4; d++) {
                float base = yy[d] * wb[d];
                t2[d*3+0] = base * e1a; t2[d*3+1] = base * e1b; t2[d*3+2] = base * e1c;
            }
            red4(ag + 96 + u0*3 + 0, t2[0], t2[1], t2[2],  t2[3]);
            red4(ag + 96 + u0*3 + 4, t2[4], t2[5], t2[6],  t2[7]);
            red4(ag + 96 + u0*3 + 8, t2[8], t2[9], t2[10], t2[11]);
        }
        // k5[u][k] = y0[u] * w5[u] * e2[k]   (cols 480 + 5u + k)
        {
            float t5[20];
            #pragma unroll
            for (int d = 0; d < 4; d++) {
                float base = yy[d] * wc[d];
                t5[d*5+0] = base*p0; t5[d*5+1] = base*p1; t5[d*5+2] = base*p2;
                t5[d*5+3] = base*p3; t5[d*5+4] = base*p4;
            }
            red4(ag + 480 + u0*5 + 0,  t5[0],  t5[1],  t5[2],  t5[3]);
            red4(ag + 480 + u0*5 + 4,  t5[4],  t5[5],  t5[6],  t5[7]);
            red4(ag + 480 + u0*5 + 8,  t5[8],  t5[9],  t5[10], t5[11]);
            red4(ag + 480 + u0*5 + 12, t5[12], t5[13], t5[14], t5[15]);
            red4(ag + 480 + u0*5 + 16, t5[16], t5[17], t5[18], t5[19]);
        }
    }

    // ===== vector-source paths: k1 (64:96), k3 (288:384), k4 (384:480), k6 (800:960) =====
    // M = sum_j e2[j] * B_j  (symmetric), coords (y,z,x)
    float Myy = -p2 * IS6 - p4 * IS2;
    float Mzz =  2.f * p2 * IS6;
    float Mxx = -p2 * IS6 + p4 * IS2;
    float Myz =  p1 * IS2;
    float Myx =  p0 * IS2;
    float Mzx =  p3 * IS2;

    const float* yv1 = ys + 64;
    for (int v0 = 0; v0 < 32; v0 += 4) {
        float4 q0 = *reinterpret_cast<const float4*>(yv1 + v0 * 3);
        float4 q1 = *reinterpret_cast<const float4*>(yv1 + v0 * 3 + 4);
        float4 q2 = *reinterpret_cast<const float4*>(yv1 + v0 * 3 + 8);
        float u[4][3] = {{q0.x, q0.y, q0.z}, {q0.w, q1.x, q1.y},
                         {q1.z, q1.w, q2.x}, {q2.y, q2.z, q2.w}};
        float wC[4] = {0,0,0,0}, wD[4] = {0,0,0,0}, wE[4] = {0,0,0,0}, wF[4] = {0,0,0,0};
        const float* wrow = s_w1 + v0;
        #pragma unroll
        for (int c = 0; c < 64; c++) {
            float hc = h[c];
            const float* r = wrow + c * 320;
            float4 a  = *reinterpret_cast<const float4*>(r + 192);  // w3
            float4 b  = *reinterpret_cast<const float4*>(r + 224);  // w1
            float4 cc = *reinterpret_cast<const float4*>(r + 256);  // w6
            float4 dd = *reinterpret_cast<const float4*>(r + 288);  // w4
            wC[0] = fmaf(hc, a.x,  wC[0]); wC[1] = fmaf(hc, a.y,  wC[1]);
            wC[2] = fmaf(hc, a.z,  wC[2]); wC[3] = fmaf(hc, a.w,  wC[3]);
            wD[0] = fmaf(hc, b.x,  wD[0]); wD[1] = fmaf(hc, b.y,  wD[1]);
            wD[2] = fmaf(hc, b.z,  wD[2]); wD[3] = fmaf(hc, b.w,  wD[3]);
            wE[0] = fmaf(hc, cc.x, wE[0]); wE[1] = fmaf(hc, cc.y, wE[1]);
            wE[2] = fmaf(hc, cc.z, wE[2]); wE[3] = fmaf(hc, cc.w, wE[3]);
            wF[0] = fmaf(hc, dd.x, wF[0]); wF[1] = fmaf(hc, dd.y, wF[1]);
            wF[2] = fmaf(hc, dd.z, wF[2]); wF[3] = fmaf(hc, dd.w, wF[3]);
        }
        // k1[v] = (w1[v]/sqrt3) * dot(y1[v], e1)     (cols 64 + v)
        {
            float k1v[4];
            #pragma unroll
            for (int d = 0; d < 4; d++)
                k1v[d] = INV_S3 * wD[d] * (u[d][0]*e1a + u[d][1]*e1b + u[d][2]*e1c);
            red4(ag + 64 + v0, k1v[0], k1v[1], k1v[2], k1v[3]);
        }
        // k3[v][k] = e0 * w3[v] * y1[v][k]           (cols 288 + 3v + k)
        {
            float t3[12];
            #pragma unroll
            for (int d = 0; d < 4; d++) {
                float base = e0 * wC[d];
                t3[d*3+0] = base*u[d][0]; t3[d*3+1] = base*u[d][1]; t3[d*3+2] = base*u[d][2];
            }
            red4(ag + 288 + v0*3 + 0, t3[0], t3[1], t3[2],  t3[3]);
            red4(ag + 288 + v0*3 + 4, t3[4], t3[5], t3[6],  t3[7]);
            red4(ag + 288 + v0*3 + 8, t3[8], t3[9], t3[10], t3[11]);
        }
        // k4[v][k] = sqrt(3/5) * w4[v] * (M @ y1[v])[k]   (cols 384 + 3v + k)
        {
            float t4[12];
            #pragma unroll
            for (int d = 0; d < 4; d++) {
                float uy = u[d][0], uz = u[d][1], ux = u[d][2];
                float s = S3_DIV_S5 * wF[d];
                t4[d*3+0] = s * (Myy*uy + Myz*uz + Myx*ux);
                t4[d*3+1] = s * (Myz*uy + Mzz*uz + Mzx*ux);
                t4[d*3+2] = s * (Myx*uy + Mzx*uz + Mxx*ux);
            }
            red4(ag + 384 + v0*3 + 0, t4[0], t4[1], t4[2],  t4[3]);
            red4(ag + 384 + v0*3 + 4, t4[4], t4[5], t4[6],  t4[7]);
            red4(ag + 384 + v0*3 + 8, t4[8], t4[9], t4[10], t4[11]);
        }
        // k6[v][k] = -w6[v] * Q_k(y1[v], e1)          (cols 800 + 5v + k)
        {
            float t6[20];
            #pragma unroll
            for (int d = 0; d < 4; d++) {
                float uy = u[d][0], uz = u[d][1], ux = u[d][2];
                float s = -wE[d];
                t6[d*5+0] = s * ((ux*e1a + uy*e1c) * IS2);
                t6[d*5+1] = s * ((uy*e1b + uz*e1a) * IS2);
                t6[d*5+2] = s * ((-uy*e1a + 2.f*uz*e1b - ux*e1c) * IS6);
                t6[d*5+3] = s * ((uz*e1c + ux*e1b) * IS2);
                t6[d*5+4] = s * ((-uy*e1a + ux*e1c) * IS2);
            }
            red4(ag + 800 + v0*5 + 0,  t6[0],  t6[1],  t6[2],  t6[3]);
            red4(ag + 800 + v0*5 + 4,  t6[4],  t6[5],  t6[6],  t6[7]);
            red4(ag + 800 + v0*5 + 8,  t6[8],  t6[9],  t6[10], t6[11]);
            red4(ag + 800 + v0*5 + 12, t6[12], t6[13], t6[14], t6[15]);
            red4(ag + 800 + v0*5 + 16, t6[16], t6[17], t6[18], t6[19]);
        }
    }
}

// ---------------- node post-linear (lin2) + combine with self-connection ----------------
__global__ __launch_bounds__(320) void k_out(
    const float* __restrict__ node_attr,
    const float* __restrict__ lin2_w0,
    const float* __restrict__ lin2_w1,
    const float* __restrict__ lin2_w2,
    float* __restrict__ out)
{
    __shared__ float m[960];
    __shared__ float sv[160];
    int n = blockIdx.x, t = threadIdx.x;
    for (int i = t; i < 960; i += 320) m[i] = g_agg[n * 960 + i];
    if (t < 160) sv[t] = g_s[n * 160 + t];
    __syncthreads();
    float a = node_attr[n];
    if (t < 64) {
        float acc = 0.f;
        #pragma unroll
        for (int p = 0; p < 96; p++) acc = fmaf(m[p], lin2_w0[p * 64 + t], acc);
        float o = acc * a * INV_S96;
        out[n * 320 + t] = C_S * sv[t] + C_X * o;
    } else if (t < 160) {
        int j = t - 64, v = j / 3, i = j - 3 * v;
        float acc = 0.f;
        #pragma unroll
        for (int p = 0; p < 128; p++) acc = fmaf(m[96 + p * 3 + i], lin2_w1[p * 32 + v], acc);
        float o = acc * a * INV_S128;
        out[n * 320 + t] = C_S * sv[t] + C_X * o;
    } else {
        int j = t - 160, v = j / 5, i = j - 5 * v;
        float acc = 0.f;
        #pragma unroll
        for (int p = 0; p < 96; p++) acc = fmaf(m[480 + p * 5 + i], lin2_w2[p * 32 + v], acc);
        float o = acc * a * INV_S96;
        out[n * 320 + t] = o;
    }
}

extern "C" void kernel_launch(void* const* d_in, const int* in_sizes, int n_in,
                              void* d_out, int out_size)
{
    const float* node_input = (const float*)d_in[0];
    const float* node_attr  = (const float*)d_in[1];
    const int*   edge_src   = (const int*)  d_in[2];
    const int*   edge_dst   = (const int*)  d_in[3];
    const float* edge_attr  = (const float*)d_in[4];
    const float* ele        = (const float*)d_in[5];
    const float* sc_w0      = (const float*)d_in[6];
    const float* sc_w1      = (const float*)d_in[7];
    const float* lin1_w0    = (const float*)d_in[8];
    const float* lin1_w1    = (const float*)d_in[9];
    const float* fc_w0      = (const float*)d_in[10];
    const float* fc_w1      = (const float*)d_in[11];
    const float* lin2_w0    = (const float*)d_in[12];
    const float* lin2_w1    = (const float*)d_in[13];
    const float* lin2_w2    = (const float*)d_in[14];
    float* out = (float*)d_out;

    const int smem_edge = (64 * 320 + 512) * 4;   // ~84 KB
    cudaFuncSetAttribute(k_edge, cudaFuncAttributeMaxDynamicSharedMemorySize, smem_edge);

    k_zero<<<(NN * 960 / 4 + 255) / 256, 256>>>();
    k_node<<<NN, 160>>>(node_input, node_attr, sc_w0, sc_w1, lin1_w0, lin1_w1);
    k_edge<<<NE / 128, 128, smem_edge>>>(edge_attr, ele, edge_src, edge_dst, fc_w0, fc_w1);
    k_out<<<NN, 320>>>(node_attr, lin2_w0, lin2_w1, lin2_w2, out);
}